// round 13
// baseline (speedup 1.0000x reference)
#include <cuda_runtime.h>

#define RNUM 2000
#define DDIM 128
#define HNUM 4
#define CAPZ 512
#define CAPE 64
#define SPLIT 4
#define SCB 8192

// ---- packed f32x2 helpers (B300 FFMA2 path; PTX-only) ----
__device__ __forceinline__ unsigned long long pk2(float lo, float hi) {
    unsigned long long r;
    asm("mov.b64 %0, {%1, %2};" : "=l"(r) : "f"(lo), "f"(hi));
    return r;
}
__device__ __forceinline__ unsigned long long mul2(unsigned long long a,
                                                   unsigned long long b) {
    unsigned long long d;
    asm("mul.rn.f32x2 %0, %1, %2;" : "=l"(d) : "l"(a), "l"(b));
    return d;
}
__device__ __forceinline__ unsigned long long fma2(unsigned long long a,
                                                   unsigned long long b,
                                                   unsigned long long c) {
    unsigned long long d;
    asm("fma.rn.f32x2 %0, %1, %2, %3;" : "=l"(d) : "l"(a), "l"(b), "l"(c));
    return d;
}
__device__ __forceinline__ void unpk2(unsigned long long v, float& lo, float& hi) {
    asm("mov.b64 {%0, %1}, %2;" : "=f"(lo), "=f"(hi) : "l"(v));
}
__device__ __forceinline__ float hadd2(unsigned long long v) {
    float lo, hi;
    unpk2(v, lo, hi);
    return lo + hi;
}

// ---- scratch (static device globals; no allocation) ----
__device__ float g_q[DDIM];
__device__ float g_a[HNUM * DDIM];
__device__ float g_c[HNUM];
__device__ int   g_count[RNUM];
__device__ int   g_ecount[RNUM];
__device__ int   g_done[RNUM];
__device__ int   g_sorted[RNUM * CAPZ];               // row indices bucketed by zone
__device__ int   g_esrc[RNUM * CAPE];                 // edge sources bucketed by dst
__device__ float g_pxbar[RNUM * SPLIT * HNUM * DDIM]; // per-(region,sub) weighted sums
__device__ float g_pden[RNUM * SPLIT * HNUM];         // per-(region,sub) denominators
__device__ float g_hh[RNUM * DDIM];

// ---- prep: block 0 computes q, a = (q^T Wk)*log2e/sqrt(D), c; block 1 zeroes ----
__global__ void prep_kernel(const float* __restrict__ S, const float* __restrict__ Wq,
                            const float* __restrict__ bq, const float* __restrict__ Wk,
                            const float* __restrict__ bk) {
    if (blockIdx.x == 1) {
        for (int i = threadIdx.x; i < RNUM; i += blockDim.x) {
            g_count[i] = 0;
            g_ecount[i] = 0;
            g_done[i] = 0;
        }
        return;
    }
    __shared__ float sS[DDIM];
    __shared__ float sq[DDIM];
    int i = threadIdx.x;  // 128 threads
    sS[i] = S[i];
    __syncthreads();
    float qi = bq[i];
    for (int j = 0; j < DDIM; j++) qi = fmaf(sS[j], Wq[i * DDIM + j], qi);
    sq[i] = qi;
    g_q[i] = qi;
    __syncthreads();
    // fold 1/sqrt(128) AND log2(e) into the score coefficients -> bare exp2 later
    const float invs = 0.08838834764831845f * 1.4426950408889634f;
    for (int h = 0; h < HNUM; h++) {
        float s = 0.f;
        for (int d = 0; d < 32; d++)
            s = fmaf(sq[h * 32 + d], Wk[(h * 32 + d) * DDIM + i], s);
        g_a[h * DDIM + i] = s * invs;
    }
    if (i < HNUM) {
        float s = 0.f;
        for (int d = 0; d < 32; d++) s = fmaf(sq[i * 32 + d], bk[i * 32 + d], s);
        g_c[i] = s * invs;
    }
}

// ---- smem-aggregated two-phase scatter of row indices by zone ----
__global__ __launch_bounds__(256) void scatter_zone_kernel(const int* __restrict__ zone,
                                                           int N) {
    __shared__ int hist[RNUM];
    int tid = threadIdx.x;
    int base = blockIdx.x * SCB;
    int nit = N - base;
    if (nit > SCB) nit = SCB;
    for (int z = tid; z < RNUM; z += 256) hist[z] = 0;
    __syncthreads();
    int nq = nit >> 2;
    // pass 1: histogram (int4)
    for (int qi = tid; qi < nq; qi += 256) {
        int4 z = __ldg((const int4*)(zone + base) + qi);
        atomicAdd(&hist[z.x], 1);
        atomicAdd(&hist[z.y], 1);
        atomicAdd(&hist[z.z], 1);
        atomicAdd(&hist[z.w], 1);
    }
    for (int i = (nq << 2) + tid; i < nit; i += 256)
        atomicAdd(&hist[zone[base + i]], 1);
    __syncthreads();
    // reserve global ranges; hist becomes a global-position cursor
    for (int z = tid; z < RNUM; z += 256) {
        int c = hist[z];
        hist[z] = (c > 0) ? atomicAdd(&g_count[z], c) : 0;
    }
    __syncthreads();
    // pass 2: scatter
    for (int qi = tid; qi < nq; qi += 256) {
        int4 z = __ldg((const int4*)(zone + base) + qi);
        int b = base + (qi << 2);
        int p0 = atomicAdd(&hist[z.x], 1);
        int p1 = atomicAdd(&hist[z.y], 1);
        int p2 = atomicAdd(&hist[z.z], 1);
        int p3 = atomicAdd(&hist[z.w], 1);
        if (p0 < CAPZ) g_sorted[z.x * CAPZ + p0] = b;
        if (p1 < CAPZ) g_sorted[z.y * CAPZ + p1] = b + 1;
        if (p2 < CAPZ) g_sorted[z.z * CAPZ + p2] = b + 2;
        if (p3 < CAPZ) g_sorted[z.w * CAPZ + p3] = b + 3;
    }
    for (int i = (nq << 2) + tid; i < nit; i += 256) {
        int z = zone[base + i];
        int p = atomicAdd(&hist[z], 1);
        if (p < CAPZ) g_sorted[z * CAPZ + p] = base + i;
    }
}

// ---- edge scatter (tiny): bucket sources by dst ----
__global__ void scatter_edge_kernel(const int* __restrict__ adj, int E) {
    int u = blockIdx.x * blockDim.x + threadIdx.x;
    if (u < E) {
        int src = adj[u];
        int dst = adj[E + u];
        int p = atomicAdd(&g_ecount[dst], 1);
        if (p < CAPE) g_esrc[dst * CAPE + p] = src;
    }
}

// ---- 8-row coalesced GEMV with 9-shuffle joint fold (packed-FMA dots) ----
__device__ __forceinline__ float gemv8_fold(const float4* __restrict__ Wb,
                                            unsigned long long x01,
                                            unsigned long long x23, int lane) {
    const unsigned F = 0xffffffffu;
    float d[8];
#pragma unroll
    for (int k = 0; k < 8; k++) {
        float4 wv = __ldg(Wb + k * 32 + lane);
        d[k] = hadd2(fma2(pk2(wv.z, wv.w), x23, mul2(pk2(wv.x, wv.y), x01)));
    }
    bool b4 = lane & 16, b3 = lane & 8, b2 = lane & 4;
    float v0 = (b4 ? d[1] : d[0]) + __shfl_xor_sync(F, b4 ? d[0] : d[1], 16);
    float v1 = (b4 ? d[3] : d[2]) + __shfl_xor_sync(F, b4 ? d[2] : d[3], 16);
    float v2 = (b4 ? d[5] : d[4]) + __shfl_xor_sync(F, b4 ? d[4] : d[5], 16);
    float v3 = (b4 ? d[7] : d[6]) + __shfl_xor_sync(F, b4 ? d[6] : d[7], 16);
    float u0 = (b3 ? v1 : v0) + __shfl_xor_sync(F, b3 ? v0 : v1, 8);
    float u1 = (b3 ? v3 : v2) + __shfl_xor_sync(F, b3 ? v2 : v3, 8);
    float s  = (b2 ? u1 : u0) + __shfl_xor_sync(F, b2 ? u0 : u1, 4);
    s += __shfl_xor_sync(F, s, 2);
    s += __shfl_xor_sync(F, s, 1);
    return s;
}

// ---- partial + fused finalize. 128 threads; blockIdx = region*SPLIT + sub.
// Streaming inner loop uses packed f32x2 FMAs for score dots and accumulators.
__global__ __launch_bounds__(128, 6) void partial_kernel(
    const float* __restrict__ x,
    const float* __restrict__ Wv, const float* __restrict__ bv,
    const float* __restrict__ Wo, const float* __restrict__ bo,
    const float* __restrict__ Wg) {
    __shared__ float swacc[4][HNUM][DDIM];   // 8 KB
    __shared__ float swden[4][HNUM];
    __shared__ float sxbar[HNUM][DDIM];      // 2 KB (finalize phase)
    __shared__ float sden[HNUM];
    __shared__ float sO[DDIM];
    __shared__ float sO2[DDIM];
    __shared__ int s_last;

    const unsigned F = 0xffffffffu;
    int rb = blockIdx.x;
    int r = rb >> 2, sub = rb & 3;
    int tid = threadIdx.x;
    int w = tid >> 5, lane = tid & 31;
    int lh = lane & 3;

    int cnt = g_count[r];
    if (cnt > CAPZ) cnt = CAPZ;
    int q4 = (((cnt + 3) >> 2) + 3) & ~3;  // rows per sub, rounded to multiple of 4
    int begin = sub * q4;
    if (begin > cnt) begin = cnt;
    int end = begin + q4;
    if (end > cnt) end = cnt;
    const int* lst = g_sorted + r * CAPZ;

    // score coefficients, packed in pairs: apk[h][0]={a[h][4l],a[h][4l+1]}, etc.
    unsigned long long apk[HNUM][2];
#pragma unroll
    for (int h = 0; h < HNUM; h++) {
        float4 a4 = __ldg((const float4*)(g_a + h * DDIM) + lane);
        apk[h][0] = pk2(a4.x, a4.y);
        apk[h][1] = pk2(a4.z, a4.w);
    }
    float cper = g_c[lh];

    // packed accumulators: accP[k][p] = {acc[k][2p], acc[k][2p+1]}; head = lh^k
    unsigned long long accP[4][2];
    float den[4] = {0.f, 0.f, 0.f, 0.f};
#pragma unroll
    for (int k = 0; k < 4; k++) {
        accP[k][0] = 0ull;
        accP[k][1] = 0ull;
    }

    // one row's full update; `valid` is warp-uniform (compile-folds on fast path)
    auto dorow = [&](const float4& xv, bool valid) {
        unsigned long long x01 = pk2(xv.x, xv.y);
        unsigned long long x23 = pk2(xv.z, xv.w);
        float p0 = hadd2(fma2(apk[0][1], x23, mul2(apk[0][0], x01)));
        float p1 = hadd2(fma2(apk[1][1], x23, mul2(apk[1][0], x01)));
        float p2 = hadd2(fma2(apk[2][1], x23, mul2(apk[2][0], x01)));
        float p3 = hadd2(fma2(apk[3][1], x23, mul2(apk[3][0], x01)));
        bool b0 = lane & 1;
        bool b1 = lane & 2;
        float rA = (b0 ? p1 : p0) + __shfl_xor_sync(F, b0 ? p0 : p1, 1);
        float rB = (b0 ? p3 : p2) + __shfl_xor_sync(F, b0 ? p2 : p3, 1);
        float rr = (b1 ? rB : rA) + __shfl_xor_sync(F, b1 ? rA : rB, 2);
        rr += __shfl_xor_sync(F, rr, 4);
        rr += __shfl_xor_sync(F, rr, 8);
        rr += __shfl_xor_sync(F, rr, 16);
        float e0 = valid ? exp2f(rr + cper) : 0.f;    // coeffs pre-scaled by log2e
        float e1 = __shfl_xor_sync(F, e0, 1);
        float e2 = __shfl_xor_sync(F, e0, 2);
        float e3 = __shfl_xor_sync(F, e0, 3);
        den[0] += e0; den[1] += e1; den[2] += e2; den[3] += e3;
        unsigned long long E0 = pk2(e0, e0);
        unsigned long long E1 = pk2(e1, e1);
        unsigned long long E2 = pk2(e2, e2);
        unsigned long long E3 = pk2(e3, e3);
        accP[0][0] = fma2(E0, x01, accP[0][0]);
        accP[0][1] = fma2(E0, x23, accP[0][1]);
        accP[1][0] = fma2(E1, x01, accP[1][0]);
        accP[1][1] = fma2(E1, x23, accP[1][1]);
        accP[2][0] = fma2(E2, x01, accP[2][0]);
        accP[2][1] = fma2(E2, x23, accP[2][1]);
        accP[3][0] = fma2(E3, x01, accP[3][0]);
        accP[3][1] = fma2(E3, x23, accP[3][1]);
    };

    int myb = begin + w * 4;
    if (myb < end) {
        int4 idx = *(const int4*)(lst + myb);  // myb is a multiple of 4
        int base = myb;
        for (;;) {
            float4 v0, v1, v2, v3;
            bool full = (base + 4 <= end);
            if (full) {
                v0 = __ldcs((const float4*)(x + (size_t)idx.x * DDIM) + lane);
                v1 = __ldcs((const float4*)(x + (size_t)idx.y * DDIM) + lane);
                v2 = __ldcs((const float4*)(x + (size_t)idx.z * DDIM) + lane);
                v3 = __ldcs((const float4*)(x + (size_t)idx.w * DDIM) + lane);
            } else {
                int last = end - 1;
                int i0 = base + 0 > last ? last : base + 0;
                int i1 = base + 1 > last ? last : base + 1;
                int i2 = base + 2 > last ? last : base + 2;
                int i3 = base + 3 > last ? last : base + 3;
                v0 = __ldcs((const float4*)(x + (size_t)lst[i0] * DDIM) + lane);
                v1 = __ldcs((const float4*)(x + (size_t)lst[i1] * DDIM) + lane);
                v2 = __ldcs((const float4*)(x + (size_t)lst[i2] * DDIM) + lane);
                v3 = __ldcs((const float4*)(x + (size_t)lst[i3] * DDIM) + lane);
            }
            int nb = base + 16;  // 4 warps * 4 rows
            bool more = nb < end;
            if (more) idx = *(const int4*)(lst + nb);  // next indices overlap compute
            if (full) {
                dorow(v0, true);
                dorow(v1, true);
                dorow(v2, true);
                dorow(v3, true);
            } else {
                dorow(v0, base + 0 < end);
                dorow(v1, base + 1 < end);
                dorow(v2, base + 2 < end);
                dorow(v3, base + 3 < end);
            }
            if (!more) break;
            base = nb;
        }
    }
    // stage per-warp partials: accP[k] belongs to head lh^k, dims 4*lane..+3
#pragma unroll
    for (int k = 0; k < 4; k++) {
        int h = lh ^ k;
        float a0, a1, a2, a3;
        unpk2(accP[k][0], a0, a1);
        unpk2(accP[k][1], a2, a3);
        swacc[w][h][lane * 4 + 0] = a0;
        swacc[w][h][lane * 4 + 1] = a1;
        swacc[w][h][lane * 4 + 2] = a2;
        swacc[w][h][lane * 4 + 3] = a3;
    }
    if (lane < 4) {
#pragma unroll
        for (int k = 0; k < 4; k++) swden[w][lh ^ k] = den[k];
    }
    __syncthreads();
    // block-reduce across 4 warps and write partials (coalesced)
    for (int p = tid; p < HNUM * DDIM; p += 128) {
        int h = p >> 7, j = p & 127;
        g_pxbar[(size_t)rb * (HNUM * DDIM) + p] =
            swacc[0][h][j] + swacc[1][h][j] + swacc[2][h][j] + swacc[3][h][j];
    }
    if (tid < HNUM)
        g_pden[rb * HNUM + tid] =
            swden[0][tid] + swden[1][tid] + swden[2][tid] + swden[3][tid];

    // ---- last-done sub-block runs finalize for this region ----
    __threadfence();
    __syncthreads();
    if (tid == 0) s_last = (atomicAdd(&g_done[r], 1) == SPLIT - 1);
    __syncthreads();
    if (!s_last) return;
    __threadfence();

    // reduce SPLIT partials (just written -> L2-hot); bypass L1
    for (int p = tid; p < HNUM * DDIM; p += 128) {
        size_t b = (size_t)r * SPLIT * (HNUM * DDIM);
        float s = __ldcg(&g_pxbar[b + p]) + __ldcg(&g_pxbar[b + 512 + p]) +
                  __ldcg(&g_pxbar[b + 1024 + p]) + __ldcg(&g_pxbar[b + 1536 + p]);
        sxbar[p >> 7][p & 127] = s;
    }
    if (tid < HNUM) {
        int b = r * SPLIT * HNUM;
        sden[tid] = __ldcg(&g_pden[b + tid]) + __ldcg(&g_pden[b + 4 + tid]) +
                    __ldcg(&g_pden[b + 8 + tid]) + __ldcg(&g_pden[b + 12 + tid]);
    }
    __syncthreads();

    int rowsel = ((lane >> 4) & 1) | (((lane >> 3) & 1) << 1) | (((lane >> 2) & 1) << 2);
    bool isw = (lane & 3) == 0;
    // ---- stage 1: O = q + (Wv . xbar[head]) / den + bv ; warp w == head w
    {
        float dn = sden[w];
        float inv = (dn > 0.f) ? (1.f / dn) : 0.f;
        float4 xv = ((const float4*)&sxbar[w][0])[lane];
        unsigned long long x01 = pk2(xv.x, xv.y), x23 = pk2(xv.z, xv.w);
        const float4* Wb = (const float4*)(Wv + (w * 32) * DDIM);
#pragma unroll
        for (int t = 0; t < 4; t++) {
            float s = gemv8_fold(Wb + t * 8 * 32, x01, x23, lane);
            if (isw) {
                int row = w * 32 + t * 8 + rowsel;
                float pooled = (dn > 0.f) ? (s * inv + bv[row]) : 0.f;
                sO[row] = g_q[row] + pooled;
            }
        }
    }
    __syncthreads();
    // ---- stage 2: O2 = O + relu(Wo . O + bo)
    {
        float4 xv = ((const float4*)sO)[lane];
        unsigned long long x01 = pk2(xv.x, xv.y), x23 = pk2(xv.z, xv.w);
        const float4* Wb = (const float4*)(Wo + (w * 32) * DDIM);
#pragma unroll
        for (int t = 0; t < 4; t++) {
            float s = gemv8_fold(Wb + t * 8 * 32, x01, x23, lane);
            if (isw) {
                int row = w * 32 + t * 8 + rowsel;
                sO2[row] = sO[row] + fmaxf(s + bo[row], 0.f);
            }
        }
    }
    __syncthreads();
    // ---- stage 3: hh = Wg . O2
    {
        float4 xv = ((const float4*)sO2)[lane];
        unsigned long long x01 = pk2(xv.x, xv.y), x23 = pk2(xv.z, xv.w);
        const float4* Wb = (const float4*)(Wg + (w * 32) * DDIM);
#pragma unroll
        for (int t = 0; t < 4; t++) {
            float s = gemv8_fold(Wb + t * 8 * 32, x01, x23, lane);
            if (isw) {
                int row = w * 32 + t * 8 + rowsel;
                g_hh[r * DDIM + row] = s;
            }
        }
    }
}

// ---- GCN gather (bucketed by dst) + self loop + bias + PReLU ----
__global__ void gather_kernel(const float* __restrict__ bg,
                              const float* __restrict__ prelu_w,
                              float* __restrict__ out) {
    int r = blockIdx.x, i = threadIdx.x;
    int ec = g_ecount[r];
    int ecl = (ec > CAPE) ? CAPE : ec;
    float degr = (float)(ec + 1);
    float disr = rsqrtf(degr);
    float accv = g_hh[r * DDIM + i] / degr;  // self-loop: dis_r^2
    const int* es = g_esrc + r * CAPE;
    for (int k = 0; k < ecl; k++) {
        int src = es[k];
        float nrm = disr * rsqrtf((float)(g_ecount[src] + 1));
        accv = fmaf(nrm, g_hh[src * DDIM + i], accv);
    }
    float v = accv + bg[i];
    out[r * DDIM + i] = (v > 0.f) ? v : prelu_w[i] * v;
}

extern "C" void kernel_launch(void* const* d_in, const int* in_sizes, int n_in,
                              void* d_out, int out_size) {
    const float* x    = (const float*)d_in[0];
    const int*   zone = (const int*)d_in[1];
    const int*   adj  = (const int*)d_in[2];
    const float* S    = (const float*)d_in[3];
    const float* Wq   = (const float*)d_in[4];
    const float* bq   = (const float*)d_in[5];
    const float* Wk   = (const float*)d_in[6];
    const float* bk   = (const float*)d_in[7];
    const float* Wv   = (const float*)d_in[8];
    const float* bv   = (const float*)d_in[9];
    const float* Wo   = (const float*)d_in[10];
    const float* bo   = (const float*)d_in[11];
    const float* Wg   = (const float*)d_in[12];
    const float* bg   = (const float*)d_in[13];
    const float* pw   = (const float*)d_in[14];
    int N = in_sizes[0] / DDIM;
    int E = in_sizes[2] / 2;

    prep_kernel<<<2, 128>>>(S, Wq, bq, Wk, bk);
    scatter_zone_kernel<<<(N + SCB - 1) / SCB, 256>>>(zone, N);
    scatter_edge_kernel<<<(E + 255) / 256, 256>>>(adj, E);
    partial_kernel<<<RNUM * SPLIT, 128>>>(x, Wv, bv, Wo, bo, Wg);
    gather_kernel<<<RNUM, DDIM>>>(bg, pw, (float*)d_out);
}

// round 14
// speedup vs baseline: 1.0063x; 1.0063x over previous
#include <cuda_runtime.h>

#define RNUM 2000
#define DDIM 128
#define HNUM 4
#define CAPZ 512
#define CAPE 64
#define SPLIT 4
#define SCB 8192

// ---- cp.async helpers ----
__device__ __forceinline__ void cpa16(unsigned smem, const void* g) {
    asm volatile("cp.async.cg.shared.global [%0], [%1], 16;" :: "r"(smem), "l"(g)
                 : "memory");
}
#define CPA_COMMIT() asm volatile("cp.async.commit_group;" ::: "memory")
#define CPA_WAIT1()  asm volatile("cp.async.wait_group 1;" ::: "memory")
#define CPA_WAIT0()  asm volatile("cp.async.wait_group 0;" ::: "memory")

// ---- scratch (static device globals; no allocation) ----
__device__ float g_q[DDIM];
__device__ float g_a[HNUM * DDIM];
__device__ float g_c[HNUM];
__device__ int   g_count[RNUM];
__device__ int   g_ecount[RNUM];
__device__ int   g_done[RNUM];
__device__ int   g_sorted[RNUM * CAPZ];               // row indices bucketed by zone
__device__ int   g_esrc[RNUM * CAPE];                 // edge sources bucketed by dst
__device__ float g_pxbar[RNUM * SPLIT * HNUM * DDIM]; // per-(region,sub) weighted sums
__device__ float g_pden[RNUM * SPLIT * HNUM];         // per-(region,sub) denominators
__device__ float g_hh[RNUM * DDIM];

// ---- prep: block 0 computes q, a = (q^T Wk)*log2e/sqrt(D), c; block 1 zeroes ----
__global__ void prep_kernel(const float* __restrict__ S, const float* __restrict__ Wq,
                            const float* __restrict__ bq, const float* __restrict__ Wk,
                            const float* __restrict__ bk) {
    if (blockIdx.x == 1) {
        for (int i = threadIdx.x; i < RNUM; i += blockDim.x) {
            g_count[i] = 0;
            g_ecount[i] = 0;
            g_done[i] = 0;
        }
        return;
    }
    __shared__ float sS[DDIM];
    __shared__ float sq[DDIM];
    int i = threadIdx.x;  // 128 threads
    sS[i] = S[i];
    __syncthreads();
    float qi = bq[i];
    for (int j = 0; j < DDIM; j++) qi = fmaf(sS[j], Wq[i * DDIM + j], qi);
    sq[i] = qi;
    g_q[i] = qi;
    __syncthreads();
    // fold 1/sqrt(128) AND log2(e) into the score coefficients -> bare exp2 later
    const float invs = 0.08838834764831845f * 1.4426950408889634f;
    for (int h = 0; h < HNUM; h++) {
        float s = 0.f;
        for (int d = 0; d < 32; d++)
            s = fmaf(sq[h * 32 + d], Wk[(h * 32 + d) * DDIM + i], s);
        g_a[h * DDIM + i] = s * invs;
    }
    if (i < HNUM) {
        float s = 0.f;
        for (int d = 0; d < 32; d++) s = fmaf(sq[i * 32 + d], bk[i * 32 + d], s);
        g_c[i] = s * invs;
    }
}

// ---- smem-aggregated two-phase scatter of row indices by zone ----
__global__ __launch_bounds__(256) void scatter_zone_kernel(const int* __restrict__ zone,
                                                           int N) {
    __shared__ int hist[RNUM];
    int tid = threadIdx.x;
    int base = blockIdx.x * SCB;
    int nit = N - base;
    if (nit > SCB) nit = SCB;
    for (int z = tid; z < RNUM; z += 256) hist[z] = 0;
    __syncthreads();
    int nq = nit >> 2;
    for (int qi = tid; qi < nq; qi += 256) {
        int4 z = __ldg((const int4*)(zone + base) + qi);
        atomicAdd(&hist[z.x], 1);
        atomicAdd(&hist[z.y], 1);
        atomicAdd(&hist[z.z], 1);
        atomicAdd(&hist[z.w], 1);
    }
    for (int i = (nq << 2) + tid; i < nit; i += 256)
        atomicAdd(&hist[zone[base + i]], 1);
    __syncthreads();
    for (int z = tid; z < RNUM; z += 256) {
        int c = hist[z];
        hist[z] = (c > 0) ? atomicAdd(&g_count[z], c) : 0;
    }
    __syncthreads();
    for (int qi = tid; qi < nq; qi += 256) {
        int4 z = __ldg((const int4*)(zone + base) + qi);
        int b = base + (qi << 2);
        int p0 = atomicAdd(&hist[z.x], 1);
        int p1 = atomicAdd(&hist[z.y], 1);
        int p2 = atomicAdd(&hist[z.z], 1);
        int p3 = atomicAdd(&hist[z.w], 1);
        if (p0 < CAPZ) g_sorted[z.x * CAPZ + p0] = b;
        if (p1 < CAPZ) g_sorted[z.y * CAPZ + p1] = b + 1;
        if (p2 < CAPZ) g_sorted[z.z * CAPZ + p2] = b + 2;
        if (p3 < CAPZ) g_sorted[z.w * CAPZ + p3] = b + 3;
    }
    for (int i = (nq << 2) + tid; i < nit; i += 256) {
        int z = zone[base + i];
        int p = atomicAdd(&hist[z], 1);
        if (p < CAPZ) g_sorted[z * CAPZ + p] = base + i;
    }
}

// ---- edge scatter (tiny): bucket sources by dst ----
__global__ void scatter_edge_kernel(const int* __restrict__ adj, int E) {
    int u = blockIdx.x * blockDim.x + threadIdx.x;
    if (u < E) {
        int src = adj[u];
        int dst = adj[E + u];
        int p = atomicAdd(&g_ecount[dst], 1);
        if (p < CAPE) g_esrc[dst * CAPE + p] = src;
    }
}

// ---- 8-row coalesced GEMV with 9-shuffle joint fold ----
__device__ __forceinline__ float gemv8_fold(const float4* __restrict__ Wb,
                                            float4 xv, int lane) {
    const unsigned F = 0xffffffffu;
    float d[8];
#pragma unroll
    for (int k = 0; k < 8; k++) {
        float4 wv = __ldg(Wb + k * 32 + lane);
        float t = wv.x * xv.x;
        t = fmaf(wv.y, xv.y, t);
        t = fmaf(wv.z, xv.z, t);
        t = fmaf(wv.w, xv.w, t);
        d[k] = t;
    }
    bool b4 = lane & 16, b3 = lane & 8, b2 = lane & 4;
    float v0 = (b4 ? d[1] : d[0]) + __shfl_xor_sync(F, b4 ? d[0] : d[1], 16);
    float v1 = (b4 ? d[3] : d[2]) + __shfl_xor_sync(F, b4 ? d[2] : d[3], 16);
    float v2 = (b4 ? d[5] : d[4]) + __shfl_xor_sync(F, b4 ? d[4] : d[5], 16);
    float v3 = (b4 ? d[7] : d[6]) + __shfl_xor_sync(F, b4 ? d[6] : d[7], 16);
    float u0 = (b3 ? v1 : v0) + __shfl_xor_sync(F, b3 ? v0 : v1, 8);
    float u1 = (b3 ? v3 : v2) + __shfl_xor_sync(F, b3 ? v2 : v3, 8);
    float s  = (b2 ? u1 : u0) + __shfl_xor_sync(F, b2 ? u0 : u1, 4);
    s += __shfl_xor_sync(F, s, 2);
    s += __shfl_xor_sync(F, s, 1);
    return s;
}

// ---- shared-memory layout: x staging buffers (streaming) UNION reduce state ----
struct RedSM {
    float swacc[4][HNUM][DDIM];  // 8 KB
    float swden[4][HNUM];
    float sxbar[HNUM][DDIM];     // 2 KB
    float sden[HNUM];
    float sO[DDIM];
    float sO2[DDIM];
};
union PartialSM {
    float xbuf[4][2][4][DDIM];   // 16 KB: [warp][stage][row][dim]
    RedSM red;
};

// ---- partial + fused finalize. 128 threads; blockIdx = region*SPLIT + sub.
// Gathered x rows staged through smem via double-buffered cp.async.cg (L1
// bypass, register-free MLP). Each lane copies and later reads ITS OWN 16B.
__global__ __launch_bounds__(128, 7) void partial_kernel(
    const float* __restrict__ x,
    const float* __restrict__ Wv, const float* __restrict__ bv,
    const float* __restrict__ Wo, const float* __restrict__ bo,
    const float* __restrict__ Wg) {
    __shared__ PartialSM sm;
    __shared__ int s_last;

    const unsigned F = 0xffffffffu;
    int rb = blockIdx.x;
    int r = rb >> 2, sub = rb & 3;
    int tid = threadIdx.x;
    int w = tid >> 5, lane = tid & 31;
    int lh = lane & 3;

    int cnt = g_count[r];
    if (cnt > CAPZ) cnt = CAPZ;
    int q4 = (((cnt + 3) >> 2) + 3) & ~3;  // rows per sub, rounded to multiple of 4
    int begin = sub * q4;
    if (begin > cnt) begin = cnt;
    int end = begin + q4;
    if (end > cnt) end = cnt;
    const int* lst = g_sorted + r * CAPZ;

    float areg[HNUM][4];
#pragma unroll
    for (int h = 0; h < HNUM; h++) {
        float4 a4 = __ldg((const float4*)(g_a + h * DDIM) + lane);
        areg[h][0] = a4.x; areg[h][1] = a4.y; areg[h][2] = a4.z; areg[h][3] = a4.w;
    }
    float cper = g_c[lh];

    float acc[4][4];
    float den[4] = {0.f, 0.f, 0.f, 0.f};
#pragma unroll
    for (int k = 0; k < 4; k++)
#pragma unroll
        for (int j = 0; j < 4; j++) acc[k][j] = 0.f;

    // one row's full update; `valid` is warp-uniform (compile-folds on fast path)
    auto dorow = [&](const float4& xv, bool valid) {
        float p0 = areg[0][0] * xv.x;
        p0 = fmaf(areg[0][1], xv.y, p0);
        p0 = fmaf(areg[0][2], xv.z, p0);
        p0 = fmaf(areg[0][3], xv.w, p0);
        float p1 = areg[1][0] * xv.x;
        p1 = fmaf(areg[1][1], xv.y, p1);
        p1 = fmaf(areg[1][2], xv.z, p1);
        p1 = fmaf(areg[1][3], xv.w, p1);
        float p2 = areg[2][0] * xv.x;
        p2 = fmaf(areg[2][1], xv.y, p2);
        p2 = fmaf(areg[2][2], xv.z, p2);
        p2 = fmaf(areg[2][3], xv.w, p2);
        float p3 = areg[3][0] * xv.x;
        p3 = fmaf(areg[3][1], xv.y, p3);
        p3 = fmaf(areg[3][2], xv.z, p3);
        p3 = fmaf(areg[3][3], xv.w, p3);
        bool b0 = lane & 1;
        bool b1 = lane & 2;
        float rA = (b0 ? p1 : p0) + __shfl_xor_sync(F, b0 ? p0 : p1, 1);
        float rB = (b0 ? p3 : p2) + __shfl_xor_sync(F, b0 ? p2 : p3, 1);
        float rr = (b1 ? rB : rA) + __shfl_xor_sync(F, b1 ? rA : rB, 2);
        rr += __shfl_xor_sync(F, rr, 4);
        rr += __shfl_xor_sync(F, rr, 8);
        rr += __shfl_xor_sync(F, rr, 16);
        float e0 = valid ? exp2f(rr + cper) : 0.f;    // coeffs pre-scaled by log2e
        float e1 = __shfl_xor_sync(F, e0, 1);
        float e2 = __shfl_xor_sync(F, e0, 2);
        float e3 = __shfl_xor_sync(F, e0, 3);
        den[0] += e0; den[1] += e1; den[2] += e2; den[3] += e3;
        acc[0][0] = fmaf(e0, xv.x, acc[0][0]);
        acc[0][1] = fmaf(e0, xv.y, acc[0][1]);
        acc[0][2] = fmaf(e0, xv.z, acc[0][2]);
        acc[0][3] = fmaf(e0, xv.w, acc[0][3]);
        acc[1][0] = fmaf(e1, xv.x, acc[1][0]);
        acc[1][1] = fmaf(e1, xv.y, acc[1][1]);
        acc[1][2] = fmaf(e1, xv.z, acc[1][2]);
        acc[1][3] = fmaf(e1, xv.w, acc[1][3]);
        acc[2][0] = fmaf(e2, xv.x, acc[2][0]);
        acc[2][1] = fmaf(e2, xv.y, acc[2][1]);
        acc[2][2] = fmaf(e2, xv.z, acc[2][2]);
        acc[2][3] = fmaf(e2, xv.w, acc[2][3]);
        acc[3][0] = fmaf(e3, xv.x, acc[3][0]);
        acc[3][1] = fmaf(e3, xv.y, acc[3][1]);
        acc[3][2] = fmaf(e3, xv.z, acc[3][2]);
        acc[3][3] = fmaf(e3, xv.w, acc[3][3]);
    };

    // issue one group's cp.async copies (4 rows, this lane's 16B of each)
    auto issue_grp = [&](int b, int stage) {
        unsigned sb = (unsigned)__cvta_generic_to_shared(&sm.xbuf[w][stage][0][0]) +
                      (unsigned)(lane * 16);
        if (b + 4 <= end) {
            int4 id = *(const int4*)(lst + b);
            cpa16(sb + 0 * 512, x + (size_t)id.x * DDIM + lane * 4);
            cpa16(sb + 1 * 512, x + (size_t)id.y * DDIM + lane * 4);
            cpa16(sb + 2 * 512, x + (size_t)id.z * DDIM + lane * 4);
            cpa16(sb + 3 * 512, x + (size_t)id.w * DDIM + lane * 4);
        } else {
            int last = end - 1;
#pragma unroll
            for (int u = 0; u < 4; u++) {
                int i = b + u;
                if (i > last) i = last;
                cpa16(sb + u * 512, x + (size_t)lst[i] * DDIM + lane * 4);
            }
        }
        CPA_COMMIT();
    };

    int myb = begin + w * 4;
    if (myb < end) {
        issue_grp(myb, 0);
        int base = myb;
        int stage = 0;
        for (;;) {
            int nb = base + 16;  // 4 warps * 4 rows
            bool more = nb < end;
            if (more) {
                issue_grp(nb, stage ^ 1);
                CPA_WAIT1();  // oldest (current) group complete
            } else {
                CPA_WAIT0();
            }
            const float4* rp = (const float4*)&sm.xbuf[w][stage][0][0];
            float4 v0 = rp[lane];
            float4 v1 = rp[32 + lane];
            float4 v2 = rp[64 + lane];
            float4 v3 = rp[96 + lane];
            if (base + 4 <= end) {
                dorow(v0, true);
                dorow(v1, true);
                dorow(v2, true);
                dorow(v3, true);
            } else {
                dorow(v0, base + 0 < end);
                dorow(v1, base + 1 < end);
                dorow(v2, base + 2 < end);
                dorow(v3, base + 3 < end);
            }
            if (!more) break;
            base = nb;
            stage ^= 1;
        }
    }
    // all warps must finish streaming before the union is reused for reduction
    __syncthreads();
    // stage per-warp partials: acc[k] belongs to head lh^k, dims 4*lane..+3
#pragma unroll
    for (int k = 0; k < 4; k++) {
        int h = lh ^ k;
        sm.red.swacc[w][h][lane * 4 + 0] = acc[k][0];
        sm.red.swacc[w][h][lane * 4 + 1] = acc[k][1];
        sm.red.swacc[w][h][lane * 4 + 2] = acc[k][2];
        sm.red.swacc[w][h][lane * 4 + 3] = acc[k][3];
    }
    if (lane < 4) {
#pragma unroll
        for (int k = 0; k < 4; k++) sm.red.swden[w][lh ^ k] = den[k];
    }
    __syncthreads();
    // block-reduce across 4 warps and write partials (coalesced)
    for (int p = tid; p < HNUM * DDIM; p += 128) {
        int h = p >> 7, j = p & 127;
        g_pxbar[(size_t)rb * (HNUM * DDIM) + p] =
            sm.red.swacc[0][h][j] + sm.red.swacc[1][h][j] +
            sm.red.swacc[2][h][j] + sm.red.swacc[3][h][j];
    }
    if (tid < HNUM)
        g_pden[rb * HNUM + tid] =
            sm.red.swden[0][tid] + sm.red.swden[1][tid] +
            sm.red.swden[2][tid] + sm.red.swden[3][tid];

    // ---- last-done sub-block runs finalize for this region ----
    __threadfence();
    __syncthreads();
    if (tid == 0) s_last = (atomicAdd(&g_done[r], 1) == SPLIT - 1);
    __syncthreads();
    if (!s_last) return;
    __threadfence();

    // reduce SPLIT partials (just written -> L2-hot); bypass L1
    for (int p = tid; p < HNUM * DDIM; p += 128) {
        size_t b = (size_t)r * SPLIT * (HNUM * DDIM);
        float s = __ldcg(&g_pxbar[b + p]) + __ldcg(&g_pxbar[b + 512 + p]) +
                  __ldcg(&g_pxbar[b + 1024 + p]) + __ldcg(&g_pxbar[b + 1536 + p]);
        sm.red.sxbar[p >> 7][p & 127] = s;
    }
    if (tid < HNUM) {
        int b = r * SPLIT * HNUM;
        sm.red.sden[tid] = __ldcg(&g_pden[b + tid]) + __ldcg(&g_pden[b + 4 + tid]) +
                           __ldcg(&g_pden[b + 8 + tid]) + __ldcg(&g_pden[b + 12 + tid]);
    }
    __syncthreads();

    int rowsel = ((lane >> 4) & 1) | (((lane >> 3) & 1) << 1) | (((lane >> 2) & 1) << 2);
    bool isw = (lane & 3) == 0;
    // ---- stage 1: O = q + (Wv . xbar[head]) / den + bv ; warp w == head w
    {
        float dn = sm.red.sden[w];
        float inv = (dn > 0.f) ? (1.f / dn) : 0.f;
        float4 xv = ((const float4*)&sm.red.sxbar[w][0])[lane];
        const float4* Wb = (const float4*)(Wv + (w * 32) * DDIM);
#pragma unroll
        for (int t = 0; t < 4; t++) {
            float s = gemv8_fold(Wb + t * 8 * 32, xv, lane);
            if (isw) {
                int row = w * 32 + t * 8 + rowsel;
                float pooled = (dn > 0.f) ? (s * inv + bv[row]) : 0.f;
                sm.red.sO[row] = g_q[row] + pooled;
            }
        }
    }
    __syncthreads();
    // ---- stage 2: O2 = O + relu(Wo . O + bo)
    {
        float4 xv = ((const float4*)sm.red.sO)[lane];
        const float4* Wb = (const float4*)(Wo + (w * 32) * DDIM);
#pragma unroll
        for (int t = 0; t < 4; t++) {
            float s = gemv8_fold(Wb + t * 8 * 32, xv, lane);
            if (isw) {
                int row = w * 32 + t * 8 + rowsel;
                sm.red.sO2[row] = sm.red.sO[row] + fmaxf(s + bo[row], 0.f);
            }
        }
    }
    __syncthreads();
    // ---- stage 3: hh = Wg . O2
    {
        float4 xv = ((const float4*)sm.red.sO2)[lane];
        const float4* Wb = (const float4*)(Wg + (w * 32) * DDIM);
#pragma unroll
        for (int t = 0; t < 4; t++) {
            float s = gemv8_fold(Wb + t * 8 * 32, xv, lane);
            if (isw) {
                int row = w * 32 + t * 8 + rowsel;
                g_hh[r * DDIM + row] = s;
            }
        }
    }
}

// ---- GCN gather (bucketed by dst) + self loop + bias + PReLU ----
__global__ void gather_kernel(const float* __restrict__ bg,
                              const float* __restrict__ prelu_w,
                              float* __restrict__ out) {
    int r = blockIdx.x, i = threadIdx.x;
    int ec = g_ecount[r];
    int ecl = (ec > CAPE) ? CAPE : ec;
    float degr = (float)(ec + 1);
    float disr = rsqrtf(degr);
    float accv = g_hh[r * DDIM + i] / degr;  // self-loop: dis_r^2
    const int* es = g_esrc + r * CAPE;
    for (int k = 0; k < ecl; k++) {
        int src = es[k];
        float nrm = disr * rsqrtf((float)(g_ecount[src] + 1));
        accv = fmaf(nrm, g_hh[src * DDIM + i], accv);
    }
    float v = accv + bg[i];
    out[r * DDIM + i] = (v > 0.f) ? v : prelu_w[i] * v;
}

extern "C" void kernel_launch(void* const* d_in, const int* in_sizes, int n_in,
                              void* d_out, int out_size) {
    const float* x    = (const float*)d_in[0];
    const int*   zone = (const int*)d_in[1];
    const int*   adj  = (const int*)d_in[2];
    const float* S    = (const float*)d_in[3];
    const float* Wq   = (const float*)d_in[4];
    const float* bq   = (const float*)d_in[5];
    const float* Wk   = (const float*)d_in[6];
    const float* bk   = (const float*)d_in[7];
    const float* Wv   = (const float*)d_in[8];
    const float* bv   = (const float*)d_in[9];
    const float* Wo   = (const float*)d_in[10];
    const float* bo   = (const float*)d_in[11];
    const float* Wg   = (const float*)d_in[12];
    const float* bg   = (const float*)d_in[13];
    const float* pw   = (const float*)d_in[14];
    int N = in_sizes[0] / DDIM;
    int E = in_sizes[2] / 2;

    prep_kernel<<<2, 128>>>(S, Wq, bq, Wk, bk);
    scatter_zone_kernel<<<(N + SCB - 1) / SCB, 256>>>(zone, N);
    scatter_edge_kernel<<<(E + 255) / 256, 256>>>(adj, E);
    partial_kernel<<<RNUM * SPLIT, 128>>>(x, Wv, bv, Wo, bo, Wg);
    gather_kernel<<<RNUM, DDIM>>>(bg, pw, (float*)d_out);
}